// round 2
// baseline (speedup 1.0000x reference)
#include <cuda_runtime.h>
#include <cstdint>

// Problem dims (fixed by the dataset)
#define M_DIM 8192
#define K_DIM 4096
#define N_DIM 11008
#define G_DIM 32
#define NPACK 1376   // N/8
#define KPACK 512    // K/8

// Dequantized weights scratch: [K, N] fp32 row-major (180.4 MB)
__device__ float W_deq[(size_t)K_DIM * N_DIM];

// ---------------------------------------------------------------------------
// f32x2 packed-FMA helpers (Blackwell sm_100+ only via PTX)
// ---------------------------------------------------------------------------
__device__ __forceinline__ unsigned long long pack2_dup(float x) {
    unsigned long long r;
    asm("mov.b64 %0, {%1,%1};" : "=l"(r) : "f"(x));
    return r;
}
__device__ __forceinline__ unsigned long long fma2(unsigned long long a,
                                                   unsigned long long b,
                                                   unsigned long long c) {
    unsigned long long d;
    asm("fma.rn.f32x2 %0, %1, %2, %3;" : "=l"(d) : "l"(a), "l"(b), "l"(c));
    return d;
}

// ---------------------------------------------------------------------------
// Kernel 1: GPTQ dequant -> W_deq[k][n] = scale[g,n] * (q[k,n] - (zero[g,n]+1))
//   qweight: [K/8, N] int32, nibbles along K (bit 4*j -> k = kp*8+j)
//   qzeros : [G, N/8] int32, nibbles along N (bit 4*j -> n = np*8+j)
//   scales : [G, N] fp32
// grid (43, 512) x 256 threads: n = bx*256+tid (43*256 == 11008), kp = by
// ---------------------------------------------------------------------------
__global__ void dequant_kernel(const int* __restrict__ qweight,
                               const int* __restrict__ qzeros,
                               const float* __restrict__ scales) {
    int n  = blockIdx.x * 256 + threadIdx.x;   // 0..11007
    int kp = blockIdx.y;                       // 0..511
    int g  = kp >> 4;                          // (kp*8)/128

    unsigned int zpack = (unsigned int)qzeros[g * NPACK + (n >> 3)];
    int zq = (int)((zpack >> ((n & 7) * 4)) & 0xFu) + 1;
    float s = scales[g * N_DIM + n];
    unsigned int packed = (unsigned int)qweight[kp * N_DIM + n];

    size_t base = (size_t)(kp * 8) * N_DIM + (size_t)n;
#pragma unroll
    for (int j = 0; j < 8; ++j) {
        int q = (int)((packed >> (4 * j)) & 0xFu);
        W_deq[base + (size_t)j * N_DIM] = s * (float)(q - zq);
    }
}

// ---------------------------------------------------------------------------
// Kernel 2: C[M,N] = A[M,K] * W_deq[K,N], fp32, packed f32x2 FMA
// 128x128 CTA tile, BK=16, 256 threads, 8x8 per thread (acc as 32 f32x2,
// pairs along n). As holds duplicated pairs so a-operands are single LDS.64;
// Bs pairs come for free by reinterpreting LDS.128 results as ulonglong2.
// All dims divide tiles exactly: 8192/128=64, 11008/128=86, 4096/16=256.
// ---------------------------------------------------------------------------
#define BM 128
#define BN 128
#define BK 16
#define TM 8
#define TN 8

__global__ __launch_bounds__(256, 2)
void gemm_f32x2_kernel(const float* __restrict__ A, float* __restrict__ C) {
    __shared__ __align__(16) unsigned long long As2[BK][BM]; // duplicated pairs, 16 KB
    __shared__ __align__(16) float Bs[BK][BN];               // 8 KB

    const int tid = threadIdx.x;
    const int m0 = blockIdx.y * BM;
    const int n0 = blockIdx.x * BN;
    const int tx = tid & 15;         // 0..15 -> n sub-tile
    const int ty = tid >> 4;         // 0..15 -> m sub-tile

    // A-tile load mapping: 128 rows x 16 cols = 512 float4; 2 per thread
    const int ar = tid >> 2;               // 0..63 (and +64)
    const int ac = (tid & 3) * 4;          // 0,4,8,12
    // B-tile load mapping: 16 rows x 128 cols = 512 float4; 2 per thread
    const int br = tid >> 5;               // 0..7 (and +8)
    const int bc = (tid & 31) * 4;         // 0..124

    unsigned long long acc[TM][TN / 2];
#pragma unroll
    for (int i = 0; i < TM; ++i)
#pragma unroll
        for (int p = 0; p < TN / 2; ++p) acc[i][p] = 0ULL;

    const float* Arow0 = A + (size_t)(m0 + ar) * K_DIM;
    const float* Arow1 = A + (size_t)(m0 + ar + 64) * K_DIM;

    for (int k0 = 0; k0 < K_DIM; k0 += BK) {
        // ---- stage A (store duplicated pairs) ----
        float4 a0 = *(const float4*)(Arow0 + k0 + ac);
        float4 a1 = *(const float4*)(Arow1 + k0 + ac);
        As2[ac + 0][ar] = pack2_dup(a0.x);
        As2[ac + 1][ar] = pack2_dup(a0.y);
        As2[ac + 2][ar] = pack2_dup(a0.z);
        As2[ac + 3][ar] = pack2_dup(a0.w);
        As2[ac + 0][ar + 64] = pack2_dup(a1.x);
        As2[ac + 1][ar + 64] = pack2_dup(a1.y);
        As2[ac + 2][ar + 64] = pack2_dup(a1.z);
        As2[ac + 3][ar + 64] = pack2_dup(a1.w);
        // ---- stage B ----
        const float* Bg0 = &W_deq[(size_t)(k0 + br) * N_DIM + n0 + bc];
        const float* Bg1 = &W_deq[(size_t)(k0 + br + 8) * N_DIM + n0 + bc];
        *(float4*)&Bs[br][bc]     = *(const float4*)Bg0;
        *(float4*)&Bs[br + 8][bc] = *(const float4*)Bg1;
        __syncthreads();

#pragma unroll
        for (int kk = 0; kk < BK; ++kk) {
            unsigned long long a2[TM];
#pragma unroll
            for (int i = 0; i < TM; ++i) a2[i] = As2[kk][ty * TM + i];
            // b pairs: reinterpret two LDS.128 as 4 packed f32x2 (no MOVs)
            ulonglong2 bq0 = *(const ulonglong2*)&Bs[kk][tx * TN];
            ulonglong2 bq1 = *(const ulonglong2*)&Bs[kk][tx * TN + 4];
            unsigned long long b2[4] = {bq0.x, bq0.y, bq1.x, bq1.y};
#pragma unroll
            for (int i = 0; i < TM; ++i) {
#pragma unroll
                for (int p = 0; p < TN / 2; ++p)
                    acc[i][p] = fma2(a2[i], b2[p], acc[i][p]);
            }
        }
        __syncthreads();
    }

    // ---- epilogue: each thread writes 8 rows x 8 cols (two 16B stores/row) ----
#pragma unroll
    for (int i = 0; i < TM; ++i) {
        float* crow = C + (size_t)(m0 + ty * TM + i) * N_DIM + n0 + tx * TN;
        ulonglong2 o0; o0.x = acc[i][0]; o0.y = acc[i][1];
        ulonglong2 o1; o1.x = acc[i][2]; o1.y = acc[i][3];
        *(ulonglong2*)(crow)     = o0;
        *(ulonglong2*)(crow + 4) = o1;
    }
}

// ---------------------------------------------------------------------------
// Launch: inputs per metadata order: x, qweight, qzeros, scales
// ---------------------------------------------------------------------------
extern "C" void kernel_launch(void* const* d_in, const int* in_sizes, int n_in,
                              void* d_out, int out_size) {
    const float* x       = (const float*)d_in[0];
    const int*   qweight = (const int*)d_in[1];
    const int*   qzeros  = (const int*)d_in[2];
    const float* scales  = (const float*)d_in[3];
    float* out = (float*)d_out;

    dequant_kernel<<<dim3(N_DIM / 256, KPACK), 256>>>(qweight, qzeros, scales);
    gemm_f32x2_kernel<<<dim3(N_DIM / BN, M_DIM / BM), 256>>>(x, out);
}

// round 4
// speedup vs baseline: 7.9374x; 7.9374x over previous
#include <cuda_runtime.h>
#include <cuda_fp16.h>
#include <cstdint>

// ---------------------------------------------------------------------------
// Problem dims (fixed)
// ---------------------------------------------------------------------------
#define M_DIM 8192
#define K_DIM 4096
#define N_DIM 11008
#define NPACK 1376   // N/8

// GEMM tiling
#define BM 128
#define BN 128
#define BK 32
#define STAGES 3
#define PITCH_H 40                       // halves per smem row (80 B) -> conflict-free ldmatrix
#define A_STAGE_B (BM * PITCH_H * 2)     // 10240 B
#define B_STAGE_B (BN * PITCH_H * 2)     // 10240 B
#define STAGE_B   (A_STAGE_B + B_STAGE_B)
#define SMEM_DYN  (STAGES * STAGE_B)     // 61440 B

// Scratch (device globals; no runtime allocation)
__device__ __half A_h[(size_t)M_DIM * K_DIM];   // 67 MB
__device__ __half W_h[(size_t)N_DIM * K_DIM];   // 90 MB, [N][K] (col-major B)

// ---------------------------------------------------------------------------
// PTX helpers (base-ISA only: cp.async, ldmatrix, mma.sync)
// ---------------------------------------------------------------------------
__device__ __forceinline__ uint32_t smem_u32(const void* p) {
    uint32_t a;
    asm("{ .reg .u64 t; cvta.to.shared.u64 t, %1; cvt.u32.u64 %0, t; }"
        : "=r"(a) : "l"(p));
    return a;
}
__device__ __forceinline__ void cp_async16(uint32_t dst, const void* src) {
    asm volatile("cp.async.cg.shared.global [%0], [%1], 16;"
                 :: "r"(dst), "l"(src) : "memory");
}
__device__ __forceinline__ void cp_commit() {
    asm volatile("cp.async.commit_group;" ::: "memory");
}
template <int N>
__device__ __forceinline__ void cp_wait() {
    asm volatile("cp.async.wait_group %0;" :: "n"(N) : "memory");
}
__device__ __forceinline__ void ldmx4(uint32_t* r, uint32_t addr) {
    asm volatile("ldmatrix.sync.aligned.m8n8.x4.shared.b16 {%0,%1,%2,%3}, [%4];"
                 : "=r"(r[0]), "=r"(r[1]), "=r"(r[2]), "=r"(r[3]) : "r"(addr));
}
__device__ __forceinline__ void mma_f16(float* d, const uint32_t* a, const uint32_t* b) {
    asm volatile(
        "mma.sync.aligned.m16n8k16.row.col.f32.f16.f16.f32 "
        "{%0,%1,%2,%3}, {%4,%5,%6,%7}, {%8,%9}, {%0,%1,%2,%3};"
        : "+f"(d[0]), "+f"(d[1]), "+f"(d[2]), "+f"(d[3])
        : "r"(a[0]), "r"(a[1]), "r"(a[2]), "r"(a[3]), "r"(b[0]), "r"(b[1]));
}

// ---------------------------------------------------------------------------
// Kernel 0: x (fp32) -> A_h (fp16), 8 elems/thread
// ---------------------------------------------------------------------------
__global__ void cvt_x_kernel(const float* __restrict__ x) {
    size_t i = ((size_t)blockIdx.x * 256 + threadIdx.x) * 8;
    float4 v0 = *(const float4*)(x + i);
    float4 v1 = *(const float4*)(x + i + 4);
    __half2 h[4];
    h[0] = __floats2half2_rn(v0.x, v0.y);
    h[1] = __floats2half2_rn(v0.z, v0.w);
    h[2] = __floats2half2_rn(v1.x, v1.y);
    h[3] = __floats2half2_rn(v1.z, v1.w);
    *(uint4*)(A_h + i) = *(uint4*)h;
}

// ---------------------------------------------------------------------------
// Kernel 1: GPTQ dequant -> W_h[n][k] = fp16(scale[g,n] * (q[k,n] - zero[g,n] - 1))
// grid (43, 256) x 256; thread handles n = bx*256+tid, kp = 2*by .. +1 (32B store)
// ---------------------------------------------------------------------------
__global__ void dequant_kernel(const int* __restrict__ qweight,
                               const int* __restrict__ qzeros,
                               const float* __restrict__ scales) {
    int n   = blockIdx.x * 256 + threadIdx.x;
    int kp0 = blockIdx.y * 2;
    int g   = kp0 >> 4;

    unsigned zpack = (unsigned)qzeros[g * NPACK + (n >> 3)];
    int zq = (int)((zpack >> ((n & 7) * 4)) & 0xFu) + 1;
    float s = scales[g * N_DIM + n];

    __half2 out[8];
#pragma unroll
    for (int p = 0; p < 2; ++p) {
        unsigned packed = (unsigned)qweight[(kp0 + p) * N_DIM + n];
#pragma unroll
        for (int j = 0; j < 4; ++j) {
            int q0 = (int)((packed >> (8 * j)) & 0xFu);
            int q1 = (int)((packed >> (8 * j + 4)) & 0xFu);
            out[p * 4 + j] = __floats2half2_rn(s * (float)(q0 - zq),
                                               s * (float)(q1 - zq));
        }
    }
    __half* dst = W_h + (size_t)n * K_DIM + (size_t)kp0 * 8;
    *(uint4*)(dst)     = *(uint4*)(out);
    *(uint4*)(dst + 8) = *(uint4*)(out + 4);
}

// ---------------------------------------------------------------------------
// Kernel 2: C[M,N] = A_h[M,K] * W_h[N,K]^T via mma.sync m16n8k16 fp16->fp32
// CTA 128x128, BK=32, 3-stage cp.async pipeline, 8 warps (2Mx4N), warp 64x32.
// blockIdx.x -> M (fast), blockIdx.y -> N (L2: B slices + most of A resident).
// ---------------------------------------------------------------------------
__global__ void __launch_bounds__(256, 2)
gemm_hmma_kernel(float* __restrict__ C) {
    extern __shared__ char dynsmem[];
    const uint32_t sbase = smem_u32(dynsmem);

    const int tid  = threadIdx.x;
    const int wid  = tid >> 5;
    const int lane = tid & 31;
    const int m0 = blockIdx.x * BM;
    const int n0 = blockIdx.y * BN;
    const int wm = (wid & 1) * 64;   // warp M offset
    const int wn = (wid >> 1) * 32;  // warp N offset

    // ---- cp.async source/dest mapping: thread -> (row, 32B column) ----
    const int ld_row = tid >> 1;           // 0..127
    const int ld_kc  = (tid & 1) * 16;     // halves (32 B)
    const __half* gA = A_h + (size_t)(m0 + ld_row) * K_DIM + ld_kc;
    const __half* gB = W_h + (size_t)(n0 + ld_row) * K_DIM + ld_kc;
    const uint32_t sA_row = sbase + ld_row * (PITCH_H * 2) + ld_kc * 2;
    const uint32_t sB_row = sA_row + A_STAGE_B;

    // ---- ldmatrix lane offsets (bytes within a stage) ----
    const uint32_t a_lane = (uint32_t)(wm + (lane & 15)) * (PITCH_H * 2)
                          + ((lane >> 4) ? 16u : 0u);
    const uint32_t b_lane = A_STAGE_B
                          + (uint32_t)(wn + ((lane >> 4) & 1) * 8 + (lane & 7)) * (PITCH_H * 2)
                          + (((lane >> 3) & 1) ? 16u : 0u);

    float acc[4][4][4];
#pragma unroll
    for (int i = 0; i < 4; ++i)
#pragma unroll
        for (int t = 0; t < 4; ++t)
#pragma unroll
            for (int r = 0; r < 4; ++r) acc[i][t][r] = 0.f;

    const int NIT = K_DIM / BK;   // 128

    // ---- prologue: stages 0,1 ----
#pragma unroll
    for (int s = 0; s < STAGES - 1; ++s) {
        uint32_t so = (uint32_t)s * STAGE_B;
        const __half* a = gA + s * BK;
        const __half* b = gB + s * BK;
        cp_async16(sA_row + so,      a);
        cp_async16(sA_row + so + 16, a + 8);
        cp_async16(sB_row + so,      b);
        cp_async16(sB_row + so + 16, b + 8);
        cp_commit();
    }

    int st = 0;
    for (int it = 0; it < NIT; ++it) {
        cp_wait<STAGES - 2>();
        __syncthreads();

        // issue stage it+2 (or empty group to keep wait-count math valid)
        int kt = it + STAGES - 1;
        if (kt < NIT) {
            int s2 = kt % STAGES;
            uint32_t so = (uint32_t)s2 * STAGE_B;
            const __half* a = gA + kt * BK;
            const __half* b = gB + kt * BK;
            cp_async16(sA_row + so,      a);
            cp_async16(sA_row + so + 16, a + 8);
            cp_async16(sB_row + so,      b);
            cp_async16(sB_row + so + 16, b + 8);
        }
        cp_commit();

        const uint32_t stage = sbase + (uint32_t)st * STAGE_B;
#pragma unroll
        for (int ks = 0; ks < 2; ++ks) {
            uint32_t afr[4][4], bfr[4][2];
#pragma unroll
            for (int i = 0; i < 4; ++i)
                ldmx4(afr[i], stage + a_lane + (uint32_t)i * 16 * (PITCH_H * 2) + ks * 32);
#pragma unroll
            for (int j = 0; j < 2; ++j) {
                uint32_t r[4];
                ldmx4(r, stage + b_lane + (uint32_t)j * 16 * (PITCH_H * 2) + ks * 32);
                bfr[2 * j][0] = r[0]; bfr[2 * j][1] = r[1];
                bfr[2 * j + 1][0] = r[2]; bfr[2 * j + 1][1] = r[3];
            }
#pragma unroll
            for (int i = 0; i < 4; ++i)
#pragma unroll
                for (int t = 0; t < 4; ++t)
                    mma_f16(acc[i][t], afr[i], bfr[t]);
        }
        if (++st == STAGES) st = 0;
    }

    // ---- epilogue: direct fp32 stores ----
    const int er = lane >> 2;
    const int ec = (lane & 3) * 2;
#pragma unroll
    for (int i = 0; i < 4; ++i) {
        size_t row0 = (size_t)(m0 + wm + i * 16 + er) * N_DIM;
        size_t row1 = row0 + 8 * N_DIM;
#pragma unroll
        for (int t = 0; t < 4; ++t) {
            int col = n0 + wn + t * 8 + ec;
            *(float2*)(C + row0 + col) = make_float2(acc[i][t][0], acc[i][t][1]);
            *(float2*)(C + row1 + col) = make_float2(acc[i][t][2], acc[i][t][3]);
        }
    }
}

// ---------------------------------------------------------------------------
// Launch
// ---------------------------------------------------------------------------
extern "C" void kernel_launch(void* const* d_in, const int* in_sizes, int n_in,
                              void* d_out, int out_size) {
    const float* x       = (const float*)d_in[0];
    const int*   qweight = (const int*)d_in[1];
    const int*   qzeros  = (const int*)d_in[2];
    const float* scales  = (const float*)d_in[3];
    float* out = (float*)d_out;

    cudaFuncSetAttribute(gemm_hmma_kernel,
                         cudaFuncAttributeMaxDynamicSharedMemorySize, SMEM_DYN);

    cvt_x_kernel<<<(M_DIM * (size_t)K_DIM) / (256 * 8), 256>>>(x);
    dequant_kernel<<<dim3(N_DIM / 256, K_DIM / 16), 256>>>(qweight, qzeros, scales);
    gemm_hmma_kernel<<<dim3(M_DIM / BM, N_DIM / BN), 256, SMEM_DYN>>>(out);
}